// round 8
// baseline (speedup 1.0000x reference)
#include <cuda_runtime.h>
#include <math.h>

// ChamferLoss: predict_pc (4,3,4096), gt_pc (4,3,4096) -> scalar
// min_n ||p-g||^2 = |p|^2 + 2*min_n( h_n - p.g_n ),  h_n = 0.5|g_n|^2
//
// Single fused kernel, 512 blocks of 128 threads =
//   (4 query tiles x 16 db chunks) x 2 dirs x 4 batch.
//   - block caches a 256-pt db chunk (4 KB) as interleaved f32x2 records
//   - 8 queries/thread amortize each shared record; packed f32x2 FFMA
//   - 5 CTAs/SM (launch_bounds 128,5) -> 5 warps/SMSP for issue hiding
//   - per-(dir,b,tile) "last block" combines the 16 chunk-mins, sqrt, partial
//   - very last combining block does the final deterministic 32-way sum -> out
// Counters self-reset for graph replay; all float sums fixed-order.

#define BATCH   4
#define NPTS    4096
#define THREADS 128
#define QPT     8                        // queries per thread
#define QTILE   (THREADS * QPT)          // 1024 queries per tile
#define NTILES  (NPTS / QTILE)           // 4
#define NCHUNK  16                       // db chunks
#define DBC     (NPTS / NCHUNK)          // 256 db points per chunk
#define RECS    (DBC / 2)                // 128 interleaved 2-point records
#define NGROUPS (2 * BATCH * NTILES)     // 32

// scratch[group][chunk][query-in-tile] : 32*16*1024 floats = 2 MB
__device__ float g_scratch[NGROUPS * NCHUNK * QTILE];
__device__ float g_partials[NGROUPS];
__device__ int   g_cnt[NGROUPS];         // zero-init; self-resetting
__device__ int   g_fin;                  // zero-init; self-resetting

__device__ __forceinline__ unsigned long long pack2(float lo, float hi) {
    unsigned long long r;
    asm("mov.b64 %0, {%1, %2};" : "=l"(r) : "f"(lo), "f"(hi));
    return r;
}
__device__ __forceinline__ void unpack2(unsigned long long v, float& lo, float& hi) {
    asm("mov.b64 {%0, %1}, %2;" : "=f"(lo), "=f"(hi) : "l"(v));
}
__device__ __forceinline__ unsigned long long fma2(unsigned long long a,
                                                   unsigned long long b,
                                                   unsigned long long c) {
    unsigned long long d;
    asm("fma.rn.f32x2 %0, %1, %2, %3;" : "=l"(d) : "l"(a), "l"(b), "l"(c));
    return d;
}

__global__ __launch_bounds__(THREADS, 5)
void chamfer_fused(const float* __restrict__ predict,
                   const float* __restrict__ gt,
                   float* __restrict__ out) {
    const int tile  = blockIdx.x >> 4;     // 0..3   query tile (1024 queries)
    const int chunk = blockIdx.x & 15;     // 0..15  db chunk (256 points)
    const int dir   = blockIdx.y;          // 0: q=predict db=gt ; 1: swapped
    const int b     = blockIdx.z;
    const int tid   = threadIdx.x;
    const int group = (dir * BATCH + b) * NTILES + tile;

    const float* q  = (dir == 0) ? predict : gt;
    const float* db = (dir == 0) ? gt : predict;
    const int base  = b * 3 * NPTS;

    // Interleaved records: rec[j] = {x0,x1, y0,y1, z0,z1, h0,h1}  (4 KB)
    __shared__ float sdb[DBC * 4];

    #pragma unroll
    for (int k = tid; k < DBC; k += THREADS) {
        const int i  = chunk * DBC + k;
        const float gx = db[base + 0 * NPTS + i];
        const float gy = db[base + 1 * NPTS + i];
        const float gz = db[base + 2 * NPTS + i];
        const float h  = 0.5f * fmaf(gx, gx, fmaf(gy, gy, gz * gz));
        const int j = k >> 1, lane = k & 1;
        sdb[j * 8 + 0 + lane] = gx;
        sdb[j * 8 + 2 + lane] = gy;
        sdb[j * 8 + 4 + lane] = gz;
        sdb[j * 8 + 6 + lane] = h;
    }
    __syncthreads();

    // 8 query points per thread (negated so score = h - p.g via fma)
    unsigned long long qx2[QPT], qy2[QPT], qz2[QPT];
    const int qbase = tile * QTILE + tid;
    #pragma unroll
    for (int jq = 0; jq < QPT; ++jq) {
        const int m = qbase + jq * THREADS;
        const float px = q[base + 0 * NPTS + m];
        const float py = q[base + 1 * NPTS + m];
        const float pz = q[base + 2 * NPTS + m];
        qx2[jq] = pack2(-px, -px);
        qy2[jq] = pack2(-py, -py);
        qz2[jq] = pack2(-pz, -pz);
    }

    float mnA[QPT], mnB[QPT];
    #pragma unroll
    for (int jq = 0; jq < QPT; ++jq) { mnA[jq] = 3.4e38f; mnB[jq] = 3.4e38f; }

    const ulonglong2* s2 = (const ulonglong2*)sdb;
    #pragma unroll 4
    for (int r = 0; r < RECS; ++r) {
        const ulonglong2 A = s2[2 * r + 0];   // {x0,x1},{y0,y1}
        const ulonglong2 B = s2[2 * r + 1];   // {z0,z1},{h0,h1}
        #pragma unroll
        for (int jq = 0; jq < QPT; ++jq) {
            const unsigned long long sc =
                fma2(qx2[jq], A.x, fma2(qy2[jq], A.y, fma2(qz2[jq], B.x, B.y)));
            float lo, hi;
            unpack2(sc, lo, hi);
            mnA[jq] = fminf(mnA[jq], lo);
            mnB[jq] = fminf(mnB[jq], hi);
        }
    }

    // Write this block's chunk-min for its 1024 queries
    const int sbase = (group * NCHUNK + chunk) * QTILE;
    #pragma unroll
    for (int jq = 0; jq < QPT; ++jq)
        g_scratch[sbase + jq * THREADS + tid] = fminf(mnA[jq], mnB[jq]);

    // ---- group-last combine ----
    __shared__ int sh_last;
    __threadfence();
    if (tid == 0) {
        const int prev = atomicAdd(&g_cnt[group], 1);
        sh_last = (prev == NCHUNK - 1) ? 1 : 0;
        if (sh_last) g_cnt[group] = 0;     // reset for next replay
    }
    __syncthreads();
    if (!sh_last) return;
    __threadfence();                        // see other blocks' scratch writes

    float acc = 0.0f;
    const int cbase = group * NCHUNK * QTILE;
    #pragma unroll
    for (int jq = 0; jq < QPT; ++jq) {
        const int ql = jq * THREADS + tid;
        float s = g_scratch[cbase + ql];
        #pragma unroll
        for (int c = 1; c < NCHUNK; ++c)
            s = fminf(s, g_scratch[cbase + c * QTILE + ql]);
        const int m = tile * QTILE + ql;
        const float px = q[base + 0 * NPTS + m];
        const float py = q[base + 1 * NPTS + m];
        const float pz = q[base + 2 * NPTS + m];
        const float pp = fmaf(px, px, fmaf(py, py, pz * pz));
        const float d2 = fmaxf(fmaf(2.0f, s, pp), 0.0f);
        acc += sqrtf(d2 + 1e-8f);
    }
    acc *= (1.0f / (float)(BATCH * NPTS));

    // Block reduction -> group partial (fixed order, deterministic)
    __shared__ float red[THREADS];
    red[tid] = acc;
    __syncthreads();
    if (tid < 64) red[tid] += red[tid + 64];
    __syncthreads();
    __shared__ int sh_fin;
    if (tid < 32) {
        float v = red[tid] + red[tid + 32];
        #pragma unroll
        for (int off = 16; off > 0; off >>= 1)
            v += __shfl_down_sync(0xFFFFFFFFu, v, off);
        if (tid == 0) {
            g_partials[group] = v;
            __threadfence();
            const int prev = atomicAdd(&g_fin, 1);
            sh_fin = (prev == NGROUPS - 1) ? 1 : 0;
            if (sh_fin) g_fin = 0;          // reset for next replay
        }
    }
    __syncthreads();
    if (sh_fin) {
        __threadfence();
        if (tid == 0) {
            float t = 0.0f;
            #pragma unroll
            for (int gI = 0; gI < NGROUPS; ++gI)
                t += g_partials[gI];
            out[0] = t;
        }
    }
}

extern "C" void kernel_launch(void* const* d_in, const int* in_sizes, int n_in,
                              void* d_out, int out_size) {
    const float* predict = (const float*)d_in[0];
    const float* gt      = (const float*)d_in[1];
    float* out = (float*)d_out;

    dim3 grid(NTILES * NCHUNK, 2, BATCH);   // 64 x 2 x 4 = 512 blocks
    chamfer_fused<<<grid, THREADS>>>(predict, gt, out);
}

// round 9
// speedup vs baseline: 1.2347x; 1.2347x over previous
#include <cuda_runtime.h>
#include <math.h>

// ChamferLoss: predict_pc (4,3,4096), gt_pc (4,3,4096) -> scalar
// min_n ||p-g||^2 = |p|^2 + 2*min_n( h_n - p.g_n ),  h_n = 0.5|g_n|^2
//
// Single fused kernel, 1024 blocks of 128 threads =
//   (8 query tiles x 16 db chunks) x 2 dirs x 4 batch.
//   - block caches a 256-pt db chunk (4 KB) as interleaved f32x2 records
//   - QPT=4 queries/thread (low regs -> 6 CTAs/SM -> 6 warps/SMSP)
//   - packed f32x2 FFMA: 3 FFMA2 evaluate 2 db points per query
//   - per-(dir,b,tile) "last block" combines the 16 chunk-mins, sqrt, partial
//   - very last combining block does the final deterministic 64-way sum -> out
// Counters self-reset for graph replay; all float sums fixed-order.

#define BATCH   4
#define NPTS    4096
#define THREADS 128
#define QPT     4                        // queries per thread
#define QTILE   (THREADS * QPT)          // 512 queries per tile
#define NTILES  (NPTS / QTILE)           // 8
#define NCHUNK  16                       // db chunks
#define DBC     (NPTS / NCHUNK)          // 256 db points per chunk
#define RECS    (DBC / 2)                // 128 interleaved 2-point records
#define NGROUPS (2 * BATCH * NTILES)     // 64

// scratch[group][chunk][query-in-tile] : 64*16*512 floats = 2 MB
__device__ float g_scratch[NGROUPS * NCHUNK * QTILE];
__device__ float g_partials[NGROUPS];
__device__ int   g_cnt[NGROUPS];         // zero-init; self-resetting
__device__ int   g_fin;                  // zero-init; self-resetting

__device__ __forceinline__ unsigned long long pack2(float lo, float hi) {
    unsigned long long r;
    asm("mov.b64 %0, {%1, %2};" : "=l"(r) : "f"(lo), "f"(hi));
    return r;
}
__device__ __forceinline__ void unpack2(unsigned long long v, float& lo, float& hi) {
    asm("mov.b64 {%0, %1}, %2;" : "=f"(lo), "=f"(hi) : "l"(v));
}
__device__ __forceinline__ unsigned long long fma2(unsigned long long a,
                                                   unsigned long long b,
                                                   unsigned long long c) {
    unsigned long long d;
    asm("fma.rn.f32x2 %0, %1, %2, %3;" : "=l"(d) : "l"(a), "l"(b), "l"(c));
    return d;
}

__global__ __launch_bounds__(THREADS, 6)
void chamfer_fused(const float* __restrict__ predict,
                   const float* __restrict__ gt,
                   float* __restrict__ out) {
    const int tile  = blockIdx.x >> 4;     // 0..7   query tile (512 queries)
    const int chunk = blockIdx.x & 15;     // 0..15  db chunk (256 points)
    const int dir   = blockIdx.y;          // 0: q=predict db=gt ; 1: swapped
    const int b     = blockIdx.z;
    const int tid   = threadIdx.x;
    const int group = (dir * BATCH + b) * NTILES + tile;

    const float* q  = (dir == 0) ? predict : gt;
    const float* db = (dir == 0) ? gt : predict;
    const int base  = b * 3 * NPTS;

    // Interleaved records: rec[j] = {x0,x1, y0,y1, z0,z1, h0,h1}  (4 KB)
    __shared__ float sdb[DBC * 4];

    #pragma unroll
    for (int k = tid; k < DBC; k += THREADS) {
        const int i  = chunk * DBC + k;
        const float gx = db[base + 0 * NPTS + i];
        const float gy = db[base + 1 * NPTS + i];
        const float gz = db[base + 2 * NPTS + i];
        const float h  = 0.5f * fmaf(gx, gx, fmaf(gy, gy, gz * gz));
        const int j = k >> 1, lane = k & 1;
        sdb[j * 8 + 0 + lane] = gx;
        sdb[j * 8 + 2 + lane] = gy;
        sdb[j * 8 + 4 + lane] = gz;
        sdb[j * 8 + 6 + lane] = h;
    }
    __syncthreads();

    // 4 query points per thread (negated so score = h - p.g via fma)
    unsigned long long qx2[QPT], qy2[QPT], qz2[QPT];
    const int qbase = tile * QTILE + tid;
    #pragma unroll
    for (int jq = 0; jq < QPT; ++jq) {
        const int m = qbase + jq * THREADS;
        const float px = q[base + 0 * NPTS + m];
        const float py = q[base + 1 * NPTS + m];
        const float pz = q[base + 2 * NPTS + m];
        qx2[jq] = pack2(-px, -px);
        qy2[jq] = pack2(-py, -py);
        qz2[jq] = pack2(-pz, -pz);
    }

    float mnA[QPT], mnB[QPT];
    #pragma unroll
    for (int jq = 0; jq < QPT; ++jq) { mnA[jq] = 3.4e38f; mnB[jq] = 3.4e38f; }

    const ulonglong2* s2 = (const ulonglong2*)sdb;
    #pragma unroll 4
    for (int r = 0; r < RECS; ++r) {
        const ulonglong2 A = s2[2 * r + 0];   // {x0,x1},{y0,y1}
        const ulonglong2 B = s2[2 * r + 1];   // {z0,z1},{h0,h1}
        #pragma unroll
        for (int jq = 0; jq < QPT; ++jq) {
            const unsigned long long sc =
                fma2(qx2[jq], A.x, fma2(qy2[jq], A.y, fma2(qz2[jq], B.x, B.y)));
            float lo, hi;
            unpack2(sc, lo, hi);
            mnA[jq] = fminf(mnA[jq], lo);
            mnB[jq] = fminf(mnB[jq], hi);
        }
    }

    // Write this block's chunk-min for its 512 queries
    const int sbase = (group * NCHUNK + chunk) * QTILE;
    #pragma unroll
    for (int jq = 0; jq < QPT; ++jq)
        g_scratch[sbase + jq * THREADS + tid] = fminf(mnA[jq], mnB[jq]);

    // ---- group-last combine ----
    __shared__ int sh_last;
    __threadfence();
    if (tid == 0) {
        const int prev = atomicAdd(&g_cnt[group], 1);
        sh_last = (prev == NCHUNK - 1) ? 1 : 0;
        if (sh_last) g_cnt[group] = 0;     // reset for next replay
    }
    __syncthreads();
    if (!sh_last) return;
    __threadfence();                        // see other blocks' scratch writes

    float acc = 0.0f;
    const int cbase = group * NCHUNK * QTILE;
    #pragma unroll
    for (int jq = 0; jq < QPT; ++jq) {
        const int ql = jq * THREADS + tid;
        float s = g_scratch[cbase + ql];
        #pragma unroll
        for (int c = 1; c < NCHUNK; ++c)
            s = fminf(s, g_scratch[cbase + c * QTILE + ql]);
        const int m = tile * QTILE + ql;
        const float px = q[base + 0 * NPTS + m];
        const float py = q[base + 1 * NPTS + m];
        const float pz = q[base + 2 * NPTS + m];
        const float pp = fmaf(px, px, fmaf(py, py, pz * pz));
        const float d2 = fmaxf(fmaf(2.0f, s, pp), 0.0f);
        acc += sqrtf(d2 + 1e-8f);
    }
    acc *= (1.0f / (float)(BATCH * NPTS));

    // Block reduction -> group partial (fixed order, deterministic)
    __shared__ float red[THREADS];
    red[tid] = acc;
    __syncthreads();
    if (tid < 64) red[tid] += red[tid + 64];
    __syncthreads();
    __shared__ int sh_fin;
    if (tid < 32) {
        float v = red[tid] + red[tid + 32];
        #pragma unroll
        for (int off = 16; off > 0; off >>= 1)
            v += __shfl_down_sync(0xFFFFFFFFu, v, off);
        if (tid == 0) {
            g_partials[group] = v;
            __threadfence();
            const int prev = atomicAdd(&g_fin, 1);
            sh_fin = (prev == NGROUPS - 1) ? 1 : 0;
            if (sh_fin) g_fin = 0;          // reset for next replay
        }
    }
    __syncthreads();
    if (sh_fin) {
        __threadfence();
        if (tid == 0) {
            float t = 0.0f;
            #pragma unroll
            for (int gI = 0; gI < NGROUPS; ++gI)
                t += g_partials[gI];
            out[0] = t;
        }
    }
}

extern "C" void kernel_launch(void* const* d_in, const int* in_sizes, int n_in,
                              void* d_out, int out_size) {
    const float* predict = (const float*)d_in[0];
    const float* gt      = (const float*)d_in[1];
    float* out = (float*)d_out;

    dim3 grid(NTILES * NCHUNK, 2, BATCH);   // 128 x 2 x 4 = 1024 blocks
    chamfer_fused<<<grid, THREADS>>>(predict, gt, out);
}